// round 16
// baseline (speedup 1.0000x reference)
#include <cuda_runtime.h>
#include <cuda_fp16.h>
#include <math.h>
#include <stdint.h>

#define BB 64
#define SS 2048
#define DD 1024
#define NEGV (-1000000000.0f)

// ---------------- scratch (device globals; no allocations) ----------------
__device__ __half g_Ech[(size_t)BB * SS * DD];  // compacted fp16 E
__device__ __half g_Wh[DD * DD];                // fp16 W_enc
__device__ int g_idx[BB * SS];
__device__ int g_jof[BB * SS];
__device__ int g_cnt[BB];
__device__ int g_cntpad[BB];
__device__ float g_dec_proj[BB * DD];
__device__ float g_scores[BB * SS];
__device__ float g_attn_c[BB * SS];
__device__ float g_ctx_part[4][BB * DD];

// ---------------- helpers ----------------
__device__ __forceinline__ unsigned smem_u32(const void* p) {
    unsigned a;
    asm("{ .reg .u64 t; cvta.to.shared.u64 t, %1; cvt.u32.u64 %0, t; }"
        : "=r"(a) : "l"(p));
    return a;
}

__device__ __forceinline__ void ldsm4(unsigned r[4], unsigned addr) {
    asm volatile("ldmatrix.sync.aligned.m8n8.x4.shared.b16 {%0,%1,%2,%3}, [%4];"
                 : "=r"(r[0]), "=r"(r[1]), "=r"(r[2]), "=r"(r[3]) : "r"(addr));
}

__device__ __forceinline__ void mma_f16(float c[4], const unsigned a[4],
                                        unsigned b0, unsigned b1) {
    asm volatile(
        "mma.sync.aligned.m16n8k16.row.col.f32.f16.f16.f32 "
        "{%0,%1,%2,%3},{%4,%5,%6,%7},{%8,%9},{%0,%1,%2,%3};"
        : "+f"(c[0]), "+f"(c[1]), "+f"(c[2]), "+f"(c[3])
        : "r"(a[0]), "r"(a[1]), "r"(a[2]), "r"(a[3]), "r"(b0), "r"(b1));
}

__device__ __forceinline__ float tanha(float x) {
    float y;
    asm("tanh.approx.f32 %0, %1;" : "=f"(y) : "f"(x));
    return y;
}

__device__ __forceinline__ void cp16(unsigned dst, const void* src) {
    asm volatile("cp.async.cg.shared.global [%0], [%1], 16;"
                 :: "r"(dst), "l"(src));
}
#define CP_COMMIT() asm volatile("cp.async.commit_group;" ::: "memory")

// pack float4 -> 4 fp16 (uint2)
__device__ __forceinline__ uint2 pack_h4(float4 v) {
    uint2 r;
    asm("{ .reg .b16 a, b; cvt.rn.f16.f32 a, %1; cvt.rn.f16.f32 b, %2;"
        "  mov.b32 %0, {a, b}; }" : "=r"(r.x) : "f"(v.x), "f"(v.y));
    asm("{ .reg .b16 a, b; cvt.rn.f16.f32 a, %1; cvt.rn.f16.f32 b, %2;"
        "  mov.b32 %0, {a, b}; }" : "=r"(r.y) : "f"(v.z), "f"(v.w));
    return r;
}

// ---------------------------------------------------------------------------
// K0a: per-b mask scan -> compact index list (deterministic, ascending s)
// cntpad now 64-aligned.
// ---------------------------------------------------------------------------
__global__ __launch_bounds__(256) void mask_scan(const int* __restrict__ mask) {
    __shared__ int wsum[8];
    __shared__ int wbase[8];
    const int b = blockIdx.x, tid = threadIdx.x;
    const int lane = tid & 31, w = tid >> 5;
    const int s0 = tid * 8;
    int m[8], tot = 0;
#pragma unroll
    for (int i = 0; i < 8; i++) {
        m[i] = (mask[b * SS + s0 + i] != 0);
        tot += m[i];
    }
    int inc = tot;
#pragma unroll
    for (int off = 1; off < 32; off <<= 1) {
        int t = __shfl_up_sync(0xffffffffu, inc, off);
        if (lane >= off) inc += t;
    }
    if (lane == 31) wsum[w] = inc;
    __syncthreads();
    if (tid == 0) {
        int r = 0;
#pragma unroll
        for (int k = 0; k < 8; k++) { wbase[k] = r; r += wsum[k]; }
        g_cnt[b] = r;
        g_cntpad[b] = (r + 63) & ~63;
    }
    __syncthreads();
    int run = wbase[w] + inc - tot;
#pragma unroll
    for (int i = 0; i < 8; i++) {
        if (m[i]) {
            g_idx[b * SS + run] = s0 + i;
            g_jof[b * SS + s0 + i] = run;
            run++;
        }
    }
}

// ---------------------------------------------------------------------------
// K0b: gather unmasked E rows -> fp16 compact (zero-pad to cntpad). Grid (S/8, B).
// ---------------------------------------------------------------------------
__global__ __launch_bounds__(256) void gather_convert(
    const float* __restrict__ E) {
    const int b = blockIdx.y;
    const int j0 = blockIdx.x * 8;
    const int cnt = g_cnt[b], cpad = g_cntpad[b];
    if (j0 >= cpad) return;
    const int r = threadIdx.x >> 5, lane = threadIdx.x & 31;
    const int j = j0 + r;
    const size_t dstoff = ((size_t)b * SS + j) * DD;
    if (j < cnt) {
        const int s = g_idx[b * SS + j];
        const float4* src = (const float4*)(E + ((size_t)b * SS + s) * DD);
#pragma unroll
        for (int i = 0; i < 8; i++) {
            const int c = lane + i * 32;
            *(uint2*)(g_Ech + dstoff + c * 4) = pack_h4(src[c]);
        }
    } else if (j < cpad) {
        uint2 z = {0u, 0u};
#pragma unroll
        for (int i = 0; i < 8; i++)
            *(uint2*)(g_Ech + dstoff + (lane + i * 32) * 4) = z;
    }
}

// K0c: W -> fp16. Grid 512 x 256.
__global__ __launch_bounds__(256) void wconv(const float* __restrict__ W) {
    const int t = blockIdx.x * 256 + threadIdx.x;
    const size_t off = (size_t)t * 8;
#pragma unroll
    for (int i = 0; i < 2; i++)
        *(uint2*)(g_Wh + off + i * 4) = pack_h4(*(const float4*)(W + off + i * 4));
}

// ---------------------------------------------------------------------------
// K1: dec_proj, warp-per-output. Grid 8192 x 256 (8 warps/block).
// ---------------------------------------------------------------------------
__global__ __launch_bounds__(256) void dec_proj_warp(
    const float* __restrict__ dh, const float* __restrict__ Wdec) {
    const int o = blockIdx.x * 8 + (threadIdx.x >> 5);
    const int lane = threadIdx.x & 31;
    const int b = o >> 10, d = o & 1023;
    const float4* a = (const float4*)(dh + (size_t)b * DD);
    const float4* w = (const float4*)(Wdec + (size_t)d * DD);
    float s = 0.f;
#pragma unroll
    for (int i = 0; i < 8; i++) {
        float4 av = a[lane + i * 32];
        float4 wv = w[lane + i * 32];
        s += av.x * wv.x + av.y * wv.y + av.z * wv.z + av.w * wv.w;
    }
#pragma unroll
    for (int off = 16; off >= 1; off >>= 1)
        s += __shfl_xor_sync(0xffffffffu, s, off);
    if (lane == 0) g_dec_proj[o] = s;
}

// ---------------------------------------------------------------------------
// K2 v8: fp16 m16n8k16 GEMM, tile 64 s x 256 d per pass, 4 passes.
// k-chunks of 64 (4 k16 steps), 2-stage cp.async. Grid (S/64, B).
// 8 warps = 2 (m: 32 rows) x 4 (n: 64 cols). 64 iterations.
// smem row = 64 halfs + pad 8 = 144 B.
// ---------------------------------------------------------------------------
#define RSB 144
#define ATILEB (64 * RSB)            // 9216
#define BTILEB (256 * RSB)           // 36864
#define STAGEB (ATILEB + BTILEB)     // 46080
#define SCPO (2 * STAGEB)            // 92160: scp[4][64] floats
#define SMEM_V8 (2 * STAGEB + 1024)

__global__ __launch_bounds__(256, 2) void scores_v8(
    const float* __restrict__ v) {
    extern __shared__ char sm[];
    const unsigned sbase = smem_u32(sm);
    float* scp = (float*)(sm + SCPO);

    const int tid = threadIdx.x;
    const int lane = tid & 31, wid = tid >> 5;
    const int wm = wid & 1, wn = wid >> 1;      // 2 x 4
    const int g = lane >> 2, t4 = lane & 3;
    const int b = blockIdx.y;
    const int s0 = blockIdx.x * 64;

    const int cnt = g_cnt[b];
    if (s0 >= g_cntpad[b]) return;

    scp[tid] = 0.f;    // scp[4][64]

    const size_t eoff = ((size_t)b * SS + s0) * DD;
    const int arow = tid >> 2, aseg = tid & 3;   // A: 64 rows x 4 segs of 32B

    float acc[2][8][4];

    auto issue = [&](int it) {
        const int pass = it >> 4, kc = it & 15;
        const unsigned d0 = sbase + (unsigned)(it & 1) * STAGEB;
        const int koff = kc * 64;
        // A: 64 rows, each thread 2x16B
        const size_t es = eoff + (size_t)arow * DD + koff + aseg * 16;
        const unsigned adst = d0 + arow * RSB + aseg * 32;
        cp16(adst,      g_Ech + es);
        cp16(adst + 16, g_Ech + es + 8);
        // B: 256 rows, each thread one full row (8x16B)
        const size_t ws = (size_t)(pass * 256 + tid) * DD + koff;
        const unsigned bdst = d0 + ATILEB + tid * RSB;
#pragma unroll
        for (int i = 0; i < 8; i++)
            cp16(bdst + i * 16, g_Wh + ws + i * 8);
        CP_COMMIT();
    };

    const int lt = lane >> 3, lr = lane & 7;

    issue(0);
    for (int it = 0; it < 64; it++) {
        asm volatile("cp.async.wait_group 0;" ::: "memory");
        __syncthreads();
        if (it + 1 < 64) issue(it + 1);

        if ((it & 15) == 0) {
#pragma unroll
            for (int mt = 0; mt < 2; mt++)
#pragma unroll
                for (int j = 0; j < 8; j++)
#pragma unroll
                    for (int c = 0; c < 4; c++) acc[mt][j][c] = 0.f;
        }

        const unsigned abase = sbase + (unsigned)(it & 1) * STAGEB;
        const unsigned bbase = abase + ATILEB;

#pragma unroll
        for (int kk = 0; kk < 4; kk++) {
            unsigned ah[2][4];
#pragma unroll
            for (int mt = 0; mt < 2; mt++) {
                const int row = 32 * wm + 16 * mt + (lt & 1) * 8 + lr;
                ldsm4(ah[mt], abase + row * RSB + kk * 32 + (lt >> 1) * 16);
            }
#pragma unroll
            for (int j2 = 0; j2 < 4; j2++) {
                const int nrow = 64 * wn + 8 * (2 * j2 + (lt >> 1)) + lr;
                unsigned bb[4];
                ldsm4(bb, bbase + nrow * RSB + kk * 32 + (lt & 1) * 16);
#pragma unroll
                for (int jj = 0; jj < 2; jj++) {
                    const int j = 2 * j2 + jj;
#pragma unroll
                    for (int mt = 0; mt < 2; mt++)
                        mma_f16(acc[mt][j], ah[mt], bb[2 * jj], bb[2 * jj + 1]);
                }
            }
        }

        if ((it & 15) == 15) {
            const int pass = it >> 4;
            const float* dpb = g_dec_proj + (size_t)b * DD + pass * 256 + wn * 64;
            const float* vb = v + pass * 256 + wn * 64;
            float p[2][2] = {{0.f, 0.f}, {0.f, 0.f}};
#pragma unroll
            for (int mt = 0; mt < 2; mt++) {
#pragma unroll
                for (int j = 0; j < 8; j++) {
                    const int c0 = 8 * j + 2 * t4;
                    const float dp0 = dpb[c0], dp1 = dpb[c0 + 1];
                    const float v0 = vb[c0], v1 = vb[c0 + 1];
                    p[mt][0] += v0 * tanha(acc[mt][j][0] + dp0) +
                                v1 * tanha(acc[mt][j][1] + dp1);
                    p[mt][1] += v0 * tanha(acc[mt][j][2] + dp0) +
                                v1 * tanha(acc[mt][j][3] + dp1);
                }
            }
#pragma unroll
            for (int off = 1; off <= 2; off <<= 1)
#pragma unroll
                for (int mt = 0; mt < 2; mt++)
#pragma unroll
                    for (int rp = 0; rp < 2; rp++)
                        p[mt][rp] += __shfl_xor_sync(0xffffffffu, p[mt][rp], off);
            // scp slot (wn, row) is exclusive to this warp
            if (t4 == 0) {
#pragma unroll
                for (int mt = 0; mt < 2; mt++)
#pragma unroll
                    for (int rp = 0; rp < 2; rp++)
                        scp[wn * 64 + 32 * wm + 16 * mt + g + 8 * rp] +=
                            p[mt][rp];
            }
        }
    }

    __syncthreads();
    if (tid < 64) {
        const int j = s0 + tid;
        if (j < cnt) {
            const int s = g_idx[b * SS + j];
            g_scores[b * SS + s] =
                (scp[tid] + scp[64 + tid]) + (scp[128 + tid] + scp[192 + tid]);
        }
    }
}

// ---------------------------------------------------------------------------
// K3: masked softmax; full attn to d_out, compact attn to g_attn_c
// ---------------------------------------------------------------------------
__global__ __launch_bounds__(256) void softmax_kernel(
    const int* __restrict__ mask, float* __restrict__ out) {
    __shared__ float red[256];
    const int b = blockIdx.x;
    const int tid = threadIdx.x;
    float vals[8];
    int msk[8];
    float mx = -INFINITY;
#pragma unroll
    for (int i = 0; i < 8; i++) {
        int s = tid + i * 256;
        size_t idx = (size_t)b * SS + s;
        msk[i] = (mask[idx] != 0);
        float scv = msk[i] ? g_scores[idx] : NEGV;
        vals[i] = scv;
        mx = fmaxf(mx, scv);
    }
    red[tid] = mx;
    __syncthreads();
    for (int off = 128; off >= 1; off >>= 1) {
        if (tid < off) red[tid] = fmaxf(red[tid], red[tid + off]);
        __syncthreads();
    }
    mx = red[0];
    __syncthreads();
    float sum = 0.f;
#pragma unroll
    for (int i = 0; i < 8; i++) {
        vals[i] = __expf(vals[i] - mx);
        sum += vals[i];
    }
    red[tid] = sum;
    __syncthreads();
    for (int off = 128; off >= 1; off >>= 1) {
        if (tid < off) red[tid] += red[tid + off];
        __syncthreads();
    }
    float inv = 1.f / red[0];
#pragma unroll
    for (int i = 0; i < 8; i++) {
        int s = tid + i * 256;
        size_t idx = (size_t)b * SS + s;
        float a = vals[i] * inv;
        out[(size_t)BB * DD + idx] = a;
        if (msk[i]) g_attn_c[(size_t)b * SS + g_jof[idx]] = a;
    }
}

// ---------------------------------------------------------------------------
// K4: context over compacted fp16 E rows. Grid (4,4,B).
// Rows in [cnt, cntpad) are zero-filled in g_Ech -> safe; loop capped at cpad.
// ---------------------------------------------------------------------------
__global__ __launch_bounds__(256) void context_part() {
    __shared__ float a_s[512];
    const int b = blockIdx.z, sy = blockIdx.y;
    const int e = blockIdx.x * 256 + threadIdx.x;
    const int cnt = g_cnt[b], cpad = g_cntpad[b];
    const int lim = cpad - sy * 512;         // 64-aligned
    float* outp = &g_ctx_part[sy][(size_t)b * DD + e];
    if (lim <= 0) { *outp = 0.f; return; }
    const int jm = lim < 512 ? lim : 512;
    for (int i = threadIdx.x; i < jm; i += 256) {
        int j = sy * 512 + i;
        a_s[i] = (j < cnt) ? g_attn_c[(size_t)b * SS + j] : 0.f;
    }
    __syncthreads();
    const __half* Eb = g_Ech + ((size_t)b * SS + sy * 512) * DD + e;
    float c[4];
#pragma unroll
    for (int i = 0; i < 4; i++) c[i] = 0.f;
    for (int t = 0; t < jm; t += 4) {
#pragma unroll
        for (int i = 0; i < 4; i++)
            c[i] += a_s[t + i] * __half2float(Eb[(size_t)(t + i) * DD]);
    }
    *outp = (c[0] + c[1]) + (c[2] + c[3]);
}

__global__ __launch_bounds__(256) void ctx_reduce(float* __restrict__ out) {
    const int i = blockIdx.x * 256 + threadIdx.x;
    out[i] = (g_ctx_part[0][i] + g_ctx_part[1][i]) +
             (g_ctx_part[2][i] + g_ctx_part[3][i]);
}

// ---------------------------------------------------------------------------
extern "C" void kernel_launch(void* const* d_in, const int* in_sizes, int n_in,
                              void* d_out, int out_size) {
    const float* dh   = (const float*)d_in[0];  // [64,1024]
    const float* E    = (const float*)d_in[1];  // [64,2048,1024]
    const int*   mask = (const int*)d_in[2];    // [64,2048]
    const float* Wenc = (const float*)d_in[3];  // [1024,1024]
    const float* Wdec = (const float*)d_in[4];  // [1024,1024]
    const float* v    = (const float*)d_in[5];  // [1024]
    float* out = (float*)d_out;                 // context [64,1024] ++ attn [64,2048]

    (void)cudaFuncSetAttribute(scores_v8,
                               cudaFuncAttributeMaxDynamicSharedMemorySize,
                               SMEM_V8);

    mask_scan<<<BB, 256>>>(mask);
    dim3 gg(SS / 8, BB);
    gather_convert<<<gg, 256>>>(E);
    wconv<<<512, 256>>>(Wenc);
    dec_proj_warp<<<BB * DD / 8, 256>>>(dh, Wdec);
    dim3 g2(SS / 64, BB);
    scores_v8<<<g2, 256, SMEM_V8>>>(v);
    softmax_kernel<<<BB, 256>>>(mask, out);
    dim3 g4(4, 4, BB);
    context_part<<<g4, 256>>>();
    ctx_reduce<<<BB * DD / 256, 256>>>(out);
}

// round 17
// speedup vs baseline: 1.1059x; 1.1059x over previous
#include <cuda_runtime.h>
#include <cuda_fp16.h>
#include <math.h>
#include <stdint.h>

#define BB 64
#define SS 2048
#define DD 1024
#define NEGV (-1000000000.0f)

// ---------------- scratch (device globals; no allocations) ----------------
__device__ __half g_Ech[(size_t)BB * SS * DD];  // compacted fp16 E
__device__ __half g_Wh[DD * DD];                // fp16 W_enc
__device__ int g_idx[BB * SS];
__device__ int g_jof[BB * SS];
__device__ int g_cnt[BB];
__device__ int g_cntpad[BB];
__device__ float g_dec_proj[BB * DD];
__device__ float g_scores[BB * SS];
__device__ float g_attn_c[BB * SS];
__device__ float g_ctx_part[4][BB * DD];

// ---------------- helpers ----------------
__device__ __forceinline__ unsigned smem_u32(const void* p) {
    unsigned a;
    asm("{ .reg .u64 t; cvta.to.shared.u64 t, %1; cvt.u32.u64 %0, t; }"
        : "=r"(a) : "l"(p));
    return a;
}

__device__ __forceinline__ void ldsm4(unsigned r[4], unsigned addr) {
    asm volatile("ldmatrix.sync.aligned.m8n8.x4.shared.b16 {%0,%1,%2,%3}, [%4];"
                 : "=r"(r[0]), "=r"(r[1]), "=r"(r[2]), "=r"(r[3]) : "r"(addr));
}

__device__ __forceinline__ void mma_f16(float c[4], const unsigned a[4],
                                        unsigned b0, unsigned b1) {
    asm volatile(
        "mma.sync.aligned.m16n8k16.row.col.f32.f16.f16.f32 "
        "{%0,%1,%2,%3},{%4,%5,%6,%7},{%8,%9},{%0,%1,%2,%3};"
        : "+f"(c[0]), "+f"(c[1]), "+f"(c[2]), "+f"(c[3])
        : "r"(a[0]), "r"(a[1]), "r"(a[2]), "r"(a[3]), "r"(b0), "r"(b1));
}

__device__ __forceinline__ float tanha(float x) {
    float y;
    asm("tanh.approx.f32 %0, %1;" : "=f"(y) : "f"(x));
    return y;
}

__device__ __forceinline__ void cp16(unsigned dst, const void* src) {
    asm volatile("cp.async.cg.shared.global [%0], [%1], 16;"
                 :: "r"(dst), "l"(src));
}
#define CP_COMMIT() asm volatile("cp.async.commit_group;" ::: "memory")

// pack float4 -> 4 fp16 (uint2)
__device__ __forceinline__ uint2 pack_h4(float4 v) {
    uint2 r;
    asm("{ .reg .b16 a, b; cvt.rn.f16.f32 a, %1; cvt.rn.f16.f32 b, %2;"
        "  mov.b32 %0, {a, b}; }" : "=r"(r.x) : "f"(v.x), "f"(v.y));
    asm("{ .reg .b16 a, b; cvt.rn.f16.f32 a, %1; cvt.rn.f16.f32 b, %2;"
        "  mov.b32 %0, {a, b}; }" : "=r"(r.y) : "f"(v.z), "f"(v.w));
    return r;
}

// ---------------------------------------------------------------------------
// K0a: per-b mask scan -> compact index list (deterministic, ascending s)
// cntpad 128-aligned (scores tile M=128).
// ---------------------------------------------------------------------------
__global__ __launch_bounds__(256) void mask_scan(const int* __restrict__ mask) {
    __shared__ int wsum[8];
    __shared__ int wbase[8];
    const int b = blockIdx.x, tid = threadIdx.x;
    const int lane = tid & 31, w = tid >> 5;
    const int s0 = tid * 8;
    int m[8], tot = 0;
#pragma unroll
    for (int i = 0; i < 8; i++) {
        m[i] = (mask[b * SS + s0 + i] != 0);
        tot += m[i];
    }
    int inc = tot;
#pragma unroll
    for (int off = 1; off < 32; off <<= 1) {
        int t = __shfl_up_sync(0xffffffffu, inc, off);
        if (lane >= off) inc += t;
    }
    if (lane == 31) wsum[w] = inc;
    __syncthreads();
    if (tid == 0) {
        int r = 0;
#pragma unroll
        for (int k = 0; k < 8; k++) { wbase[k] = r; r += wsum[k]; }
        g_cnt[b] = r;
        g_cntpad[b] = (r + 127) & ~127;
    }
    __syncthreads();
    int run = wbase[w] + inc - tot;
#pragma unroll
    for (int i = 0; i < 8; i++) {
        if (m[i]) {
            g_idx[b * SS + run] = s0 + i;
            g_jof[b * SS + s0 + i] = run;
            run++;
        }
    }
}

// ---------------------------------------------------------------------------
// K0b: gather unmasked E rows -> fp16 compact (zero-pad to cntpad). Grid (S/8, B).
// ---------------------------------------------------------------------------
__global__ __launch_bounds__(256) void gather_convert(
    const float* __restrict__ E) {
    const int b = blockIdx.y;
    const int j0 = blockIdx.x * 8;
    const int cnt = g_cnt[b], cpad = g_cntpad[b];
    if (j0 >= cpad) return;
    const int r = threadIdx.x >> 5, lane = threadIdx.x & 31;
    const int j = j0 + r;
    const size_t dstoff = ((size_t)b * SS + j) * DD;
    if (j < cnt) {
        const int s = g_idx[b * SS + j];
        const float4* src = (const float4*)(E + ((size_t)b * SS + s) * DD);
#pragma unroll
        for (int i = 0; i < 8; i++) {
            const int c = lane + i * 32;
            *(uint2*)(g_Ech + dstoff + c * 4) = pack_h4(src[c]);
        }
    } else if (j < cpad) {
        uint2 z = {0u, 0u};
#pragma unroll
        for (int i = 0; i < 8; i++)
            *(uint2*)(g_Ech + dstoff + (lane + i * 32) * 4) = z;
    }
}

// K0c: W -> fp16. Grid 512 x 256.
__global__ __launch_bounds__(256) void wconv(const float* __restrict__ W) {
    const int t = blockIdx.x * 256 + threadIdx.x;
    const size_t off = (size_t)t * 8;
#pragma unroll
    for (int i = 0; i < 2; i++)
        *(uint2*)(g_Wh + off + i * 4) = pack_h4(*(const float4*)(W + off + i * 4));
}

// ---------------------------------------------------------------------------
// K1: dec_proj, warp-per-output. Grid 8192 x 256 (8 warps/block).
// ---------------------------------------------------------------------------
__global__ __launch_bounds__(256) void dec_proj_warp(
    const float* __restrict__ dh, const float* __restrict__ Wdec) {
    const int o = blockIdx.x * 8 + (threadIdx.x >> 5);
    const int lane = threadIdx.x & 31;
    const int b = o >> 10, d = o & 1023;
    const float4* a = (const float4*)(dh + (size_t)b * DD);
    const float4* w = (const float4*)(Wdec + (size_t)d * DD);
    float s = 0.f;
#pragma unroll
    for (int i = 0; i < 8; i++) {
        float4 av = a[lane + i * 32];
        float4 wv = w[lane + i * 32];
        s += av.x * wv.x + av.y * wv.y + av.z * wv.z + av.w * wv.w;
    }
#pragma unroll
    for (int off = 16; off >= 1; off >>= 1)
        s += __shfl_xor_sync(0xffffffffu, s, off);
    if (lane == 0) g_dec_proj[o] = s;
}

// ---------------------------------------------------------------------------
// K2 v7 (proven 786us config): fp16 m16n8k16 GEMM on compacted rows.
// CTA 128 s x 128 d per pass, 8 passes, k-chunks of 64 (4 k16 steps),
// 3-stage cp.async pipeline. Grid (S/128, B). 8 warps = 4 (m) x 2 (n).
// ---------------------------------------------------------------------------
#define RSB 144
#define TILEB (128 * RSB)       // 18432 per operand
#define BUFB (2 * TILEB)        // 36864 per stage (A + B)
#define NSTAGE 3
#define SCPO (NSTAGE * BUFB)
#define SMEM_V7 (NSTAGE * BUFB + 1024)

__global__ __launch_bounds__(256, 2) void scores_v7(
    const float* __restrict__ v) {
    extern __shared__ char sm[];
    const unsigned sbase = smem_u32(sm);
    float* scp = (float*)(sm + SCPO);

    const int tid = threadIdx.x;
    const int lane = tid & 31, wid = tid >> 5;
    const int wm = wid & 3, wn = wid >> 2;
    const int g = lane >> 2, t4 = lane & 3;
    const int b = blockIdx.y;
    const int s0 = blockIdx.x * 128;

    const int cnt = g_cnt[b];
    if (s0 >= g_cntpad[b]) return;

    scp[tid] = 0.f;

    const size_t eoff = ((size_t)b * SS + s0) * DD;
    const int crow = tid >> 1;        // 0..127
    const int ch = tid & 1;           // row half (32 halfs each)

    float acc[2][8][4];

    auto issue = [&](int it) {
        const int pass = it >> 4, kc = it & 15;
        const unsigned d0 = sbase + (unsigned)(it % NSTAGE) * BUFB;
        const int koff = kc * 64;
        const size_t es = eoff + (size_t)crow * DD + koff + ch * 32;
        const size_t ws = (size_t)(pass * 128 + crow) * DD + koff + ch * 32;
        const unsigned dst = d0 + crow * RSB + ch * 64;
#pragma unroll
        for (int i = 0; i < 4; i++) {
            cp16(dst + i * 16,         g_Ech + es + i * 8);
            cp16(dst + TILEB + i * 16, g_Wh + ws + i * 8);
        }
        CP_COMMIT();
    };

    const int lt = lane >> 3, lr = lane & 7;

    issue(0);
    issue(1);
    for (int it = 0; it < 128; it++) {
        asm volatile("cp.async.wait_group 1;" ::: "memory");
        __syncthreads();
        if (it + 2 < 128) issue(it + 2);

        if ((it & 15) == 0) {
#pragma unroll
            for (int mt = 0; mt < 2; mt++)
#pragma unroll
                for (int j = 0; j < 8; j++)
#pragma unroll
                    for (int c = 0; c < 4; c++) acc[mt][j][c] = 0.f;
        }

        const unsigned abase = sbase + (unsigned)(it % NSTAGE) * BUFB;
        const unsigned bbase = abase + TILEB;

#pragma unroll
        for (int kk = 0; kk < 4; kk++) {
            unsigned ah[2][4];
#pragma unroll
            for (int mt = 0; mt < 2; mt++) {
                const int row = 32 * wm + 16 * mt + (lt & 1) * 8 + lr;
                ldsm4(ah[mt], abase + row * RSB + kk * 32 + (lt >> 1) * 16);
            }
#pragma unroll
            for (int j2 = 0; j2 < 4; j2++) {
                const int nrow = 64 * wn + 8 * (2 * j2 + (lt >> 1)) + lr;
                unsigned bb[4];
                ldsm4(bb, bbase + nrow * RSB + kk * 32 + (lt & 1) * 16);
#pragma unroll
                for (int jj = 0; jj < 2; jj++) {
                    const int j = 2 * j2 + jj;
#pragma unroll
                    for (int mt = 0; mt < 2; mt++)
                        mma_f16(acc[mt][j], ah[mt], bb[2 * jj], bb[2 * jj + 1]);
                }
            }
        }

        if ((it & 15) == 15) {
            const int pass = it >> 4;
            const float* dpb = g_dec_proj + (size_t)b * DD + pass * 128 + wn * 64;
            const float* vb = v + pass * 128 + wn * 64;
            float p[2][2] = {{0.f, 0.f}, {0.f, 0.f}};
#pragma unroll
            for (int mt = 0; mt < 2; mt++) {
#pragma unroll
                for (int j = 0; j < 8; j++) {
                    const int c0 = 8 * j + 2 * t4;
                    const float dp0 = dpb[c0], dp1 = dpb[c0 + 1];
                    const float v0 = vb[c0], v1 = vb[c0 + 1];
                    p[mt][0] += v0 * tanha(acc[mt][j][0] + dp0) +
                                v1 * tanha(acc[mt][j][1] + dp1);
                    p[mt][1] += v0 * tanha(acc[mt][j][2] + dp0) +
                                v1 * tanha(acc[mt][j][3] + dp1);
                }
            }
#pragma unroll
            for (int off = 1; off <= 2; off <<= 1)
#pragma unroll
                for (int mt = 0; mt < 2; mt++)
#pragma unroll
                    for (int rp = 0; rp < 2; rp++)
                        p[mt][rp] += __shfl_xor_sync(0xffffffffu, p[mt][rp], off);
            if (t4 == 0) {
#pragma unroll
                for (int mt = 0; mt < 2; mt++)
#pragma unroll
                    for (int rp = 0; rp < 2; rp++)
                        scp[wn * 128 + 32 * wm + 16 * mt + g + 8 * rp] +=
                            p[mt][rp];
            }
        }
    }

    __syncthreads();
    if (tid < 128) {
        const int j = s0 + tid;
        if (j < cnt) {
            const int s = g_idx[b * SS + j];
            g_scores[b * SS + s] = scp[tid] + scp[128 + tid];
        }
    }
}

// ---------------------------------------------------------------------------
// K3: masked softmax; full attn to d_out, compact attn to g_attn_c.
// 512 threads, 4 elems/thread.
// ---------------------------------------------------------------------------
__global__ __launch_bounds__(512) void softmax_kernel(
    const int* __restrict__ mask, float* __restrict__ out) {
    __shared__ float red[512];
    const int b = blockIdx.x;
    const int tid = threadIdx.x;
    float vals[4];
    int msk[4];
    float mx = -INFINITY;
#pragma unroll
    for (int i = 0; i < 4; i++) {
        int s = tid + i * 512;
        size_t idx = (size_t)b * SS + s;
        msk[i] = (mask[idx] != 0);
        float scv = msk[i] ? g_scores[idx] : NEGV;
        vals[i] = scv;
        mx = fmaxf(mx, scv);
    }
    red[tid] = mx;
    __syncthreads();
    for (int off = 256; off >= 1; off >>= 1) {
        if (tid < off) red[tid] = fmaxf(red[tid], red[tid + off]);
        __syncthreads();
    }
    mx = red[0];
    __syncthreads();
    float sum = 0.f;
#pragma unroll
    for (int i = 0; i < 4; i++) {
        vals[i] = __expf(vals[i] - mx);
        sum += vals[i];
    }
    red[tid] = sum;
    __syncthreads();
    for (int off = 256; off >= 1; off >>= 1) {
        if (tid < off) red[tid] += red[tid + off];
        __syncthreads();
    }
    float inv = 1.f / red[0];
#pragma unroll
    for (int i = 0; i < 4; i++) {
        int s = tid + i * 512;
        size_t idx = (size_t)b * SS + s;
        float a = vals[i] * inv;
        out[(size_t)BB * DD + idx] = a;
        if (msk[i]) g_attn_c[(size_t)b * SS + g_jof[idx]] = a;
    }
}

// ---------------------------------------------------------------------------
// K4: context over compacted fp16 E rows. Grid (4,4,B).
// Rows in [cnt, cpad) are zero-filled in g_Ech -> safe; loop capped at cpad.
// ---------------------------------------------------------------------------
__global__ __launch_bounds__(256) void context_part() {
    __shared__ float a_s[512];
    const int b = blockIdx.z, sy = blockIdx.y;
    const int e = blockIdx.x * 256 + threadIdx.x;
    const int cnt = g_cnt[b], cpad = g_cntpad[b];
    const int lim = cpad - sy * 512;
    float* outp = &g_ctx_part[sy][(size_t)b * DD + e];
    if (lim <= 0) { *outp = 0.f; return; }
    const int jm = lim < 512 ? lim : 512;
    for (int i = threadIdx.x; i < jm; i += 256) {
        int j = sy * 512 + i;
        a_s[i] = (j < cnt) ? g_attn_c[(size_t)b * SS + j] : 0.f;
    }
    __syncthreads();
    const __half* Eb = g_Ech + ((size_t)b * SS + sy * 512) * DD + e;
    float c[4];
#pragma unroll
    for (int i = 0; i < 4; i++) c[i] = 0.f;
    for (int t = 0; t < jm; t += 4) {
#pragma unroll
        for (int i = 0; i < 4; i++)
            c[i] += a_s[t + i] * __half2float(Eb[(size_t)(t + i) * DD]);
    }
    *outp = (c[0] + c[1]) + (c[2] + c[3]);
}

__global__ __launch_bounds__(256) void ctx_reduce(float* __restrict__ out) {
    const int i = blockIdx.x * 256 + threadIdx.x;
    out[i] = (g_ctx_part[0][i] + g_ctx_part[1][i]) +
             (g_ctx_part[2][i] + g_ctx_part[3][i]);
}

// ---------------------------------------------------------------------------
extern "C" void kernel_launch(void* const* d_in, const int* in_sizes, int n_in,
                              void* d_out, int out_size) {
    const float* dh   = (const float*)d_in[0];  // [64,1024]
    const float* E    = (const float*)d_in[1];  // [64,2048,1024]
    const int*   mask = (const int*)d_in[2];    // [64,2048]
    const float* Wenc = (const float*)d_in[3];  // [1024,1024]
    const float* Wdec = (const float*)d_in[4];  // [1024,1024]
    const float* v    = (const float*)d_in[5];  // [1024]
    float* out = (float*)d_out;                 // context [64,1024] ++ attn [64,2048]

    (void)cudaFuncSetAttribute(scores_v7,
                               cudaFuncAttributeMaxDynamicSharedMemorySize,
                               SMEM_V7);

    mask_scan<<<BB, 256>>>(mask);
    dim3 gg(SS / 8, BB);
    gather_convert<<<gg, 256>>>(E);
    wconv<<<512, 256>>>(Wenc);
    dec_proj_warp<<<BB * DD / 8, 256>>>(dh, Wdec);
    dim3 g2(SS / 128, BB);
    scores_v7<<<g2, 256, SMEM_V7>>>(v);
    softmax_kernel<<<BB, 512>>>(mask, out);
    dim3 g4(4, 4, BB);
    context_part<<<g4, 256>>>();
    ctx_reduce<<<BB * DD / 256, 256>>>(out);
}